// round 4
// baseline (speedup 1.0000x reference)
#include <cuda_runtime.h>
#include <cuda_bf16.h>

// ControlledSystem derivatives, LUT-accelerated (v4).
// Friction MLP output (kinetic_mag, stiction_limit) depends only on v2.
//   kernel 1: build per-interval float4 LUT (k0, dk, s0, ds) on [-8,8],
//             8 lanes/interval (4 per endpoint), weights in shared.
//   kernel 2: per element, ONE 16B gather + lerp.

#define HID 64
#define TABLE 8192
#define NODES (TABLE + 1)
#define X0 (-8.0f)
#define X_RANGE 16.0f
#define H_STEP (X_RANGE / TABLE)
#define INV_H (TABLE / X_RANGE)

__device__ float4 g_lut[TABLE];   // (k0, k1-k0, s0, s1-s0) per interval

__device__ __forceinline__ float tanh_fast(float x) {
    float y;
    asm("tanh.approx.f32 %0, %1;" : "=f"(y) : "f"(x));
    return y;
}

__device__ __forceinline__ float softplus_f(float x) {
    return fmaxf(x, 0.0f) + log1pf(__expf(-fabsf(x)));
}

// ---------- prep: per-interval LUT, 8 lanes/interval ----------
__global__ __launch_bounds__(256)
void build_lut_kernel(const float* __restrict__ W1,
                      const float* __restrict__ B1,
                      const float* __restrict__ W2,
                      const float* __restrict__ B2)
{
    __shared__ float sW1[HID];
    __shared__ float sB1[HID];
    __shared__ float sW2[2 * HID];
    __shared__ float sB2[2];

    const int tid = threadIdx.x;
    if (tid < HID / 4) {
        reinterpret_cast<float4*>(sW1)[tid] = reinterpret_cast<const float4*>(W1)[tid];
        reinterpret_cast<float4*>(sB1)[tid] = reinterpret_cast<const float4*>(B1)[tid];
    } else if (tid < HID / 4 + HID / 2) {
        const int j = tid - HID / 4;
        reinterpret_cast<float4*>(sW2)[j] = reinterpret_cast<const float4*>(W2)[j];
    } else if (tid == 192) {
        sB2[0] = B2[0]; sB2[1] = B2[1];
    }
    __syncthreads();

    const int gtid     = blockIdx.x * blockDim.x + tid;
    const int interval = gtid >> 3;          // 8 lanes per interval
    const int sub      = gtid & 7;           // 0-3: node i, 4-7: node i+1
    if (interval >= TABLE) return;

    const int node = interval + (sub >> 2);
    const int q    = sub & 3;                // hidden chunk within endpoint

    const float v = fmaf((float)node, H_STEP, X0);

    float a0 = 0.0f, a1 = 0.0f;
    const int jbase = q * (HID / 4);
#pragma unroll
    for (int jj = 0; jj < HID / 4; jj++) {
        const int j = jbase + jj;
        const float h = tanh_fast(fmaf(v, sW1[j], sB1[j]));
        a0 = fmaf(h, sW2[2 * j],     a0);
        a1 = fmaf(h, sW2[2 * j + 1], a1);
    }
    // reduce across the 4 lanes of this endpoint
    a0 += __shfl_xor_sync(0xffffffff, a0, 1);
    a1 += __shfl_xor_sync(0xffffffff, a1, 1);
    a0 += __shfl_xor_sync(0xffffffff, a0, 2);
    a1 += __shfl_xor_sync(0xffffffff, a1, 2);

    const float Kn = softplus_f(a0 + sB2[0]);
    const float Sn = softplus_f(a1 + sB2[1]);

    // pull the i+1 endpoint values into the lower half of the 8-lane group
    const float K1 = __shfl_xor_sync(0xffffffff, Kn, 4);
    const float S1 = __shfl_xor_sync(0xffffffff, Sn, 4);

    if (sub == 0) {
        g_lut[interval] = make_float4(Kn, K1 - Kn, Sn, S1 - Sn);
    }
}

// ---------- element math ----------
__device__ __forceinline__ void element(
    float t, float x1, float v1, float x2, float v2, float xc,
    float K, float zc, float pc,
    float& dv1, float& dv2, float& dxc)
{
    const float x2ref = 0.5f * __sinf(0.5f * t);
    const float e     = x2ref - x2;
    dxc = fmaf(-pc, xc, e);
    const float u = fmaf(K * (zc - pc), xc, K * e);

    dv1 = u - 2.0f * x1 - 0.5f * v1 - 3.0f * (x1 - x2) - 0.8f * (v1 - v2);

    const float Fnet = 3.0f * (x1 - x2) + 0.8f * (v1 - v2);

    // LUT lookup: one 16B gather + lerp
    float uu = (v2 - X0) * INV_H;
    uu = fminf(fmaxf(uu, 0.0f), (float)TABLE - 0.001f);
    const int   idx = (int)uu;
    const float fr  = uu - (float)idx;
    const float4 L  = g_lut[idx];
    const float kin = fmaf(fr, L.y, L.x);
    const float stc = fmaf(fr, L.w, L.z);

    const float Ffr = (fabsf(v2) < 0.01f)
        ? -fminf(fmaxf(Fnet, -stc), stc)
        : -copysignf(kin, v2);
    dv2 = (Fnet + Ffr) * (1.0f / 1.5f);
}

// ---------- main kernel: 4 elements/thread, float4 I/O ----------
__global__ __launch_bounds__(256, 8)
void controlled_system_v4_kernel(
    const float* __restrict__ T,
    const float* __restrict__ Z,
    const float* __restrict__ logK,
    const float* __restrict__ logz,
    const float* __restrict__ logp,
    float* __restrict__ out,
    int n)   // n divisible by 4
{
    const int i4  = blockIdx.x * blockDim.x + threadIdx.x;
    const int nv4 = n >> 2;
    if (i4 >= nv4) return;

    const float K  = __expf(logK[0]);
    const float zc = __expf(logz[0]);
    const float pc = __expf(logp[0]);

    const float4 t4  = reinterpret_cast<const float4*>(T)[i4];
    const float4 x14 = reinterpret_cast<const float4*>(Z)[i4];
    const float4 v14 = reinterpret_cast<const float4*>(Z + n)[i4];
    const float4 x24 = reinterpret_cast<const float4*>(Z + 2 * (size_t)n)[i4];
    const float4 v24 = reinterpret_cast<const float4*>(Z + 3 * (size_t)n)[i4];
    const float4 xc4 = reinterpret_cast<const float4*>(Z + 4 * (size_t)n)[i4];

    float4 dv1o, dv2o, dxco;
    element(t4.x, x14.x, v14.x, x24.x, v24.x, xc4.x, K, zc, pc, dv1o.x, dv2o.x, dxco.x);
    element(t4.y, x14.y, v14.y, x24.y, v24.y, xc4.y, K, zc, pc, dv1o.y, dv2o.y, dxco.y);
    element(t4.z, x14.z, v14.z, x24.z, v24.z, xc4.z, K, zc, pc, dv1o.z, dv2o.z, dxco.z);
    element(t4.w, x14.w, v14.w, x24.w, v24.w, xc4.w, K, zc, pc, dv1o.w, dv2o.w, dxco.w);

    reinterpret_cast<float4*>(out)[i4]                 = v14;   // dx1 = v1
    reinterpret_cast<float4*>(out + n)[i4]             = dv1o;
    reinterpret_cast<float4*>(out + 2 * (size_t)n)[i4] = v24;   // dx2 = v2
    reinterpret_cast<float4*>(out + 3 * (size_t)n)[i4] = dv2o;
    reinterpret_cast<float4*>(out + 4 * (size_t)n)[i4] = dxco;
}

// ---------- scalar fallback (n not divisible by 4) ----------
__global__ __launch_bounds__(256, 8)
void controlled_system_s_kernel(
    const float* __restrict__ T,
    const float* __restrict__ Z,
    const float* __restrict__ logK,
    const float* __restrict__ logz,
    const float* __restrict__ logp,
    float* __restrict__ out,
    int n)
{
    const int i = blockIdx.x * blockDim.x + threadIdx.x;
    if (i >= n) return;
    const float K  = __expf(logK[0]);
    const float zc = __expf(logz[0]);
    const float pc = __expf(logp[0]);
    const float t  = T[i];
    const float x1 = Z[i];
    const float v1 = Z[n + i];
    const float x2 = Z[2 * (size_t)n + i];
    const float v2 = Z[3 * (size_t)n + i];
    const float xc = Z[4 * (size_t)n + i];
    float dv1, dv2, dxc;
    element(t, x1, v1, x2, v2, xc, K, zc, pc, dv1, dv2, dxc);
    out[i]                 = v1;
    out[n + i]             = dv1;
    out[2 * (size_t)n + i] = v2;
    out[3 * (size_t)n + i] = dv2;
    out[4 * (size_t)n + i] = dxc;
}

extern "C" void kernel_launch(void* const* d_in, const int* in_sizes, int n_in,
                              void* d_out, int out_size) {
    const float* T    = (const float*)d_in[0];
    const float* Z    = (const float*)d_in[1];
    const float* logK = (const float*)d_in[2];
    const float* logz = (const float*)d_in[3];
    const float* logp = (const float*)d_in[4];
    const float* W1   = (const float*)d_in[5];
    const float* B1   = (const float*)d_in[6];
    const float* W2   = (const float*)d_in[7];
    const float* B2   = (const float*)d_in[8];
    float* out = (float*)d_out;
    const int n = in_sizes[0];

    const int prep_threads = 8 * TABLE;  // 8 lanes per interval
    build_lut_kernel<<<prep_threads / 256, 256>>>(W1, B1, W2, B2);

    if ((n & 3) == 0) {
        const int nv4 = n >> 2;
        controlled_system_v4_kernel<<<(nv4 + 255) / 256, 256>>>(
            T, Z, logK, logz, logp, out, n);
    } else {
        controlled_system_s_kernel<<<(n + 255) / 256, 256>>>(
            T, Z, logK, logz, logp, out, n);
    }
}